// round 17
// baseline (speedup 1.0000x reference)
#include <cuda_runtime.h>
#include <cuda_bf16.h>
#include <cuda_fp16.h>
#include <cstdint>
#include <math.h>

#define S    3072
#define DIM  1280
#define NH   16
#define HD   80
#define SEG  512
#define NSEG 6

// ---------------- scratch (__device__ globals; no allocs allowed) ----------
__device__ __half g_ah[S * DIM];              // hidden (fp16)
__device__ __half g_wh[4 * DIM * DIM];        // weights (fp16)
__device__ __half g_ch[S * DIM];              // ctx (fp16)

// attention operands (fp16, per-head [h][S][80])
__device__ __half g_qh[NH * S * HD];
__device__ __half g_kh[NH * S * HD];
__device__ __half g_vh[NH * S * HD];

// ---------------- PTX helpers (sm_80-era, arch-neutral) --------------------
__device__ __forceinline__ uint32_t smem_u32(const void* p) {
    uint32_t a;
    asm("{ .reg .u64 t; cvta.to.shared.u64 t, %1; cvt.u32.u64 %0, t; }"
        : "=r"(a) : "l"(p));
    return a;
}
__device__ __forceinline__ void ldsm4(uint32_t* r, uint32_t addr) {
    asm volatile("ldmatrix.sync.aligned.m8n8.x4.shared.b16 {%0,%1,%2,%3}, [%4];"
                 : "=r"(r[0]), "=r"(r[1]), "=r"(r[2]), "=r"(r[3]) : "r"(addr));
}
__device__ __forceinline__ void ldsm4t(uint32_t* r, uint32_t addr) {
    asm volatile("ldmatrix.sync.aligned.m8n8.x4.trans.shared.b16 {%0,%1,%2,%3}, [%4];"
                 : "=r"(r[0]), "=r"(r[1]), "=r"(r[2]), "=r"(r[3]) : "r"(addr));
}
__device__ __forceinline__ void mma16816h(float* d, const uint32_t* a, const uint32_t* b) {
    asm volatile(
        "mma.sync.aligned.m16n8k16.row.col.f32.f16.f16.f32 "
        "{%0,%1,%2,%3}, {%4,%5,%6,%7}, {%8,%9}, {%0,%1,%2,%3};"
        : "+f"(d[0]), "+f"(d[1]), "+f"(d[2]), "+f"(d[3])
        : "r"(a[0]), "r"(a[1]), "r"(a[2]), "r"(a[3]), "r"(b[0]), "r"(b[1]));
}

#define CP_ASYNC16(dst, src) \
    asm volatile("cp.async.cg.shared.global [%0], [%1], 16;" :: "r"(dst), "l"(src))
#define CP_COMMIT() asm volatile("cp.async.commit_group;")
#define CP_WAIT1()  asm volatile("cp.async.wait_group 1;")
#define CP_WAIT0()  asm volatile("cp.async.wait_group 0;")

__device__ __forceinline__ uint32_t pkh(float x, float y) {
    __half2 H = __halves2half2(__float2half_rn(x), __float2half_rn(y));
    return *(uint32_t*)&H;
}

// ---------------- fp32 -> fp16 conversion (one launch) ----------------------
#define HS4 (S * DIM / 4)
#define W4  (DIM * DIM / 4)
__global__ void split_all(const float4* __restrict__ hs,
                          const float4* __restrict__ w0, const float4* __restrict__ w1,
                          const float4* __restrict__ w2, const float4* __restrict__ w3,
                          uint2* __restrict__ ah, uint2* __restrict__ wh) {
    int i = blockIdx.x * blockDim.x + threadIdx.x;
    if (i < HS4) {
        float4 v = hs[i];
        ah[i] = make_uint2(pkh(v.x, v.y), pkh(v.z, v.w));
    } else {
        int j = i - HS4;
        int z = j / W4, r = j - z * W4;
        const float4* s = (z == 0) ? w0 : (z == 1) ? w1 : (z == 2) ? w2 : w3;
        float4 v = s[r];
        wh[(size_t)z * W4 + r] = make_uint2(pkh(v.x, v.y), pkh(v.z, v.w));
    }
}

// ---------------- fused QKV projection + RoPE, BN=80 (one head/tile) --------
// 8 warps, each owns 16 rows x 80 cols. z: 0=Q(rope+scale), 1=K(rope), 2=V.
#define QTS 144
#define QTILE_A (128 * QTS)          // 18432
#define QTILE_B (80 * QTS)           // 11520
#define QSTAGE  (QTILE_A + QTILE_B)  // 29952
#define QKV_SMEM (2 * QSTAGE)        // 59904

__global__ __launch_bounds__(256, 2) void gemm_qkv_rope(
    const __half* __restrict__ Ahi, const __half* __restrict__ Wh_base,
    const float* __restrict__ cosb, const float* __restrict__ sinb,
    const float* __restrict__ bq, const float* __restrict__ bk, const float* __restrict__ bv,
    __half* __restrict__ qh, __half* __restrict__ kh, __half* __restrict__ vh)
{
    extern __shared__ char smem[];
    const uint32_t sb = smem_u32(smem);
    const int tid  = threadIdx.x;
    const int wid  = tid >> 5;
    const int lane = tid & 31;

    const int z = blockIdx.z;
    const int h = blockIdx.x;                 // head
    const int m0 = blockIdx.y * 128;
    const __half* Wh = Wh_base + (size_t)z * DIM * DIM + (size_t)h * HD * DIM;
    const float* bias = (z == 0) ? bq : (z == 1) ? bk : bv;

    const char* srcA = (const char*)(Ahi + (size_t)m0 * DIM);
    const char* srcB = (const char*)Wh;

    float acc[10][4];
#pragma unroll
    for (int nt = 0; nt < 10; nt++)
#pragma unroll
        for (int i = 0; i < 4; i++) acc[nt][i] = 0.f;

    auto cp_stage = [&](uint32_t dst, int k0b) {
#pragma unroll
        for (int i = 0; i < 4; i++) {          // A: 1024 cp16
            int e = i * 256 + tid;
            int row = e >> 3, c16 = e & 7;
            CP_ASYNC16(dst + row * QTS + c16 * 16,
                       srcA + (size_t)row * (DIM * 2) + k0b + c16 * 16);
        }
#pragma unroll
        for (int i = 0; i < 3; i++) {          // B: 640 cp16
            int e = i * 256 + tid;
            if (e < 640) {
                int row = e >> 3, c16 = e & 7;
                CP_ASYNC16(dst + QTILE_A + row * QTS + c16 * 16,
                           srcB + (size_t)row * (DIM * 2) + k0b + c16 * 16);
            }
        }
    };

    cp_stage(sb, 0);
    CP_COMMIT();

    const int arow = lane & 15;
    const int acolh = (lane >> 4) * 16;
    const int browa = ((lane >> 4) << 3) + (lane & 7);
    const int bcolh = ((lane >> 3) & 1) * 16;

    for (int c = 0; c < NSEG * 0 + (DIM / 64); c++) {   // 20 chunks
        if (c + 1 < DIM / 64) {
            cp_stage(sb + ((c + 1) & 1) * QSTAGE, (c + 1) * 128);
            CP_COMMIT();
            CP_WAIT1();
        } else {
            CP_WAIT0();
        }
        __syncthreads();

        const uint32_t stage = sb + (c & 1) * QSTAGE;
        const uint32_t sA = stage;
        const uint32_t sW = stage + QTILE_A;

#pragma unroll
        for (int ks = 0; ks < 4; ks++) {
            uint32_t a4[4];
            ldsm4(a4, sA + (uint32_t)((wid * 16 + arow) * QTS + ks * 32 + acolh));
#pragma unroll
            for (int ng = 0; ng < 5; ng++) {
                uint32_t b4[4];
                ldsm4(b4, sW + (uint32_t)((ng * 16 + browa) * QTS + ks * 32 + bcolh));
                mma16816h(acc[ng * 2], a4, b4);
                mma16816h(acc[ng * 2 + 1], a4, b4 + 2);
            }
        }
        __syncthreads();
    }

    // ---- epilogue: bias (+rope for q/k), write per-head fp16 ----------------
    const int r4 = lane >> 2;
    const int q2 = (lane & 3) * 2;
    const int r0 = m0 + wid * 16 + r4;        // rows r0, r0+8
    if (z == 2) {
#pragma unroll
        for (int nt = 0; nt < 10; nt++) {
            int d = nt * 8 + q2;
            float2 b2 = *(const float2*)(bias + h * HD + d);
            size_t ob = ((size_t)h * S + r0) * HD + d;
            *(uint32_t*)(vh + ob) = pkh(acc[nt][0] + b2.x, acc[nt][1] + b2.y);
            *(uint32_t*)(vh + ob + (size_t)8 * HD) =
                pkh(acc[nt][2] + b2.x, acc[nt][3] + b2.y);
        }
    } else {
        __half* dst = (z == 0) ? qh : kh;
        const float scale = (z == 0) ? 0.11180339887498949f : 1.0f;
#pragma unroll
        for (int nt = 0; nt < 5; nt++) {
            int d = nt * 8 + q2;               // d < 40
            float2 b1 = *(const float2*)(bias + h * HD + d);
            float2 b2 = *(const float2*)(bias + h * HD + d + 40);
            float2 c0 = *(const float2*)(cosb + (size_t)r0 * HD + d);
            float2 s0 = *(const float2*)(sinb + (size_t)r0 * HD + d);
            float2 c1 = *(const float2*)(cosb + (size_t)(r0 + 8) * HD + d);
            float2 s1 = *(const float2*)(sinb + (size_t)(r0 + 8) * HD + d);

            float x0  = acc[nt][0] + b1.x,     x0b = acc[nt][1] + b1.y;
            float y0  = acc[nt + 5][0] + b2.x, y0b = acc[nt + 5][1] + b2.y;
            float x1  = acc[nt][2] + b1.x,     x1b = acc[nt][3] + b1.y;
            float y1  = acc[nt + 5][2] + b2.x, y1b = acc[nt + 5][3] + b2.y;

            size_t ob = ((size_t)h * S + r0) * HD + d;
            *(uint32_t*)(dst + ob) =
                pkh((x0 * c0.x - y0 * s0.x) * scale, (x0b * c0.y - y0b * s0.y) * scale);
            *(uint32_t*)(dst + ob + 40) =
                pkh((y0 * c0.x + x0 * s0.x) * scale, (y0b * c0.y + x0b * s0.y) * scale);
            *(uint32_t*)(dst + ob + (size_t)8 * HD) =
                pkh((x1 * c1.x - y1 * s1.x) * scale, (x1b * c1.y - y1b * s1.y) * scale);
            *(uint32_t*)(dst + ob + (size_t)8 * HD + 40) =
                pkh((y1 * c1.x + x1 * s1.x) * scale, (y1b * c1.y + x1b * s1.y) * scale);
        }
    }
}

// ---------------- HMMA fp16 GEMM, BK=64 (O projection) ----------------------
#define GBM 128
#define GBN 128
#define NCHUNK (DIM / 64)
#define TSTRIDE 144
#define TILE_B  (128 * TSTRIDE)
#define STAGE_B (2 * TILE_B)
#define GEMM_SMEM (2 * STAGE_B)      // 73728

__global__ __launch_bounds__(256, 2) void gemm_hmma(
    const __half* __restrict__ Ahi,
    const __half* __restrict__ Wh_base,
    int zoff,
    const float* __restrict__ bias0,
    float* __restrict__ C0)
{
    extern __shared__ char smem[];
    const uint32_t sb = smem_u32(smem);
    const int tid  = threadIdx.x;
    const int wid  = tid >> 5;
    const int lane = tid & 31;

    const __half* Wh = Wh_base + (size_t)zoff * DIM * DIM;
    const float* bias = bias0;
    float* C = C0;

    const int m0 = blockIdx.y * GBM;
    const int n0 = blockIdx.x * GBN;
    const int wm = (wid & 1) * 64;
    const int wn = (wid >> 1) * 32;

    const char* srcs[2];
    srcs[0] = (const char*)(Ahi + (size_t)m0 * DIM);
    srcs[1] = (const char*)(Wh  + (size_t)n0 * DIM);

    float acc[4][4][4];
#pragma unroll
    for (int mt = 0; mt < 4; mt++)
#pragma unroll
        for (int nt = 0; nt < 4; nt++)
#pragma unroll
            for (int i = 0; i < 4; i++) acc[mt][nt][i] = 0.f;

    {
#pragma unroll
        for (int i = 0; i < 8; i++) {
            int t = i >> 2;
            int e = (i & 3) * 256 + tid;
            int row = e >> 3, c16 = e & 7;
            CP_ASYNC16(sb + t * TILE_B + row * TSTRIDE + c16 * 16,
                       srcs[t] + (size_t)row * (DIM * 2) + c16 * 16);
        }
        CP_COMMIT();
    }

    const int arow = lane & 15;
    const int acolh = (lane >> 4) * 16;
    const int browa = ((lane >> 4) << 3) + (lane & 7);
    const int bcolh = ((lane >> 3) & 1) * 16;

    for (int c = 0; c < NCHUNK; c++) {
        if (c + 1 < NCHUNK) {
            const int k0b = (c + 1) * 128;
            uint32_t d = sb + ((c + 1) & 1) * STAGE_B;
#pragma unroll
            for (int i = 0; i < 8; i++) {
                int t = i >> 2;
                int e = (i & 3) * 256 + tid;
                int row = e >> 3, c16 = e & 7;
                CP_ASYNC16(d + t * TILE_B + row * TSTRIDE + c16 * 16,
                           srcs[t] + (size_t)row * (DIM * 2) + k0b + c16 * 16);
            }
            CP_COMMIT();
            CP_WAIT1();
        } else {
            CP_WAIT0();
        }
        __syncthreads();

        const uint32_t stage = sb + (c & 1) * STAGE_B;
        const uint32_t sA = stage;
        const uint32_t sW = stage + TILE_B;

#pragma unroll
        for (int ks = 0; ks < 4; ks++) {
            const int acol = ks * 32 + acolh;
            uint32_t bh[8];
            {
                uint32_t boff = (uint32_t)((wn + browa) * TSTRIDE + ks * 32 + bcolh);
                ldsm4(bh,     sW + boff);
                ldsm4(bh + 4, sW + boff + 16 * TSTRIDE);
            }
#pragma unroll
            for (int mt = 0; mt < 4; mt++) {
                uint32_t ah[4];
                uint32_t off = (uint32_t)((wm + mt * 16 + arow) * TSTRIDE + acol);
                ldsm4(ah, sA + off);
#pragma unroll
                for (int nt = 0; nt < 4; nt++)
                    mma16816h(acc[mt][nt], ah, bh + nt * 2);
            }
        }
        __syncthreads();
    }

    const int r0 = lane >> 2;
    const int c0 = (lane & 3) * 2;
#pragma unroll
    for (int mt = 0; mt < 4; mt++) {
#pragma unroll
        for (int nt = 0; nt < 4; nt++) {
            int gm = m0 + wm + mt * 16 + r0;
            int gn = n0 + wn + nt * 8 + c0;
            float2 bv = *(const float2*)(bias + gn);
            float2 o0, o1;
            o0.x = acc[mt][nt][0] + bv.x;
            o0.y = acc[mt][nt][1] + bv.y;
            o1.x = acc[mt][nt][2] + bv.x;
            o1.y = acc[mt][nt][3] + bv.y;
            *(float2*)(C + (size_t)gm * DIM + gn) = o0;
            *(float2*)(C + (size_t)(gm + 8) * DIM + gn) = o1;
        }
    }
}

// ---------------- flash attention: fp16, 2 barriers/chunk (unchanged R16) ---
#define ATS 176
#define ATB (64 * ATS)
#define AQ  0
#define AK0 ATB
#define AV0 (2 * ATB)
#define AK1 (3 * ATB)
#define AV1 (4 * ATB)
#define APMAX (5 * ATB)
#define APLS  (APMAX + 512)
#define ATTN_SMEM (APLS + 256)       // 57088 B

__global__ __launch_bounds__(256, 2) void attn_mma(__half* __restrict__ ch)
{
    extern __shared__ char sm[];
    const uint32_t sb = smem_u32(sm);
    const int tid = threadIdx.x;
    const int wid = tid >> 5;
    const int lane = tid & 31;

    const int qt = blockIdx.x;
    const int h  = blockIdx.y;
    const int sg = blockIdx.z;
    const int s0 = sg * SEG;
    const int q0 = s0 + qt * 64;
    const size_t hb = (size_t)h * S * HD;

    const int wm = (wid & 3) * 16;
    const int wh = wid >> 2;
    const int wn = wh * 32;

    float* pmax = (float*)(sm + APMAX);
    float* plsum = (float*)(sm + APLS);

    const char* qhp = (const char*)(g_qh + hb + (size_t)q0 * HD);
    const char* khp = (const char*)(g_kh + hb + (size_t)s0 * HD);
    const char* vhp = (const char*)(g_vh + hb + (size_t)s0 * HD);

    auto cp_tile = [&](uint32_t dst, const char* src, int rb) {
#pragma unroll
        for (int i = 0; i < 3; i++) {
            int f = i * 256 + tid;
            if (f < 640) {
                int r = f / 10, c = f - r * 10;
                CP_ASYNC16(sb + dst + r * ATS + c * 16,
                           src + (size_t)(rb + r) * 160 + c * 16);
            }
        }
    };

    cp_tile(AQ, qhp, 0);
    cp_tile(AK0, khp, 0);
    cp_tile(AV0, vhp, 0);
    CP_COMMIT();

    float acc[10][4];
#pragma unroll
    for (int nt = 0; nt < 10; nt++)
#pragma unroll
        for (int i = 0; i < 4; i++) acc[nt][i] = 0.f;

    float mold0 = -1e30f, mold1 = -1e30f;
    float lsum0 = 0.f, lsum1 = 0.f;

    const int qrow = wm + (lane & 15);
    const uint32_t qcoloff = (uint32_t)((lane >> 4) * 16);
    const int krowa = wn + ((lane >> 4) << 3) + (lane & 7);
    const uint32_t kcoloff = (uint32_t)(((lane >> 3) & 1) * 16);
    const int r4 = lane >> 2;
    const int q2 = (lane & 3) * 2;

    for (int c = 0; c < 8; c++) {
        const uint32_t sKH = sb + ((c & 1) ? AK1 : AK0);
        const uint32_t sVH = sb + ((c & 1) ? AV1 : AV0);

        CP_WAIT0();
        __syncthreads();

        if (c + 1 < 8) {
            cp_tile((c & 1) ? AK0 : AK1, khp, (c + 1) * 64);
            cp_tile((c & 1) ? AV0 : AV1, vhp, (c + 1) * 64);
            CP_COMMIT();
        }

        float sa[4][4];
#pragma unroll
        for (int nt = 0; nt < 4; nt++)
#pragma unroll
            for (int i = 0; i < 4; i++) sa[nt][i] = 0.f;

#pragma unroll
        for (int ks = 0; ks < 5; ks++) {
            uint32_t qh4[4], kh[8];
            uint32_t qoff = (uint32_t)(qrow * ATS + ks * 32) + qcoloff;
            ldsm4(qh4, sb + AQ + qoff);
            uint32_t koff0 = (uint32_t)(krowa * ATS + ks * 32) + kcoloff;
            ldsm4(kh,     sKH + koff0);
            ldsm4(kh + 4, sKH + koff0 + 16 * ATS);
#pragma unroll
            for (int nt = 0; nt < 4; nt++)
                mma16816h(sa[nt], qh4, kh + nt * 2);
        }

        float mx0 = fmaxf(fmaxf(sa[0][0], sa[0][1]), fmaxf(sa[1][0], sa[1][1]));
        mx0 = fmaxf(mx0, fmaxf(fmaxf(sa[2][0], sa[2][1]), fmaxf(sa[3][0], sa[3][1])));
        float mx1 = fmaxf(fmaxf(sa[0][2], sa[0][3]), fmaxf(sa[1][2], sa[1][3]));
        mx1 = fmaxf(mx1, fmaxf(fmaxf(sa[2][2], sa[2][3]), fmaxf(sa[3][2], sa[3][3])));
        mx0 = fmaxf(mx0, __shfl_xor_sync(0xffffffffu, mx0, 1));
        mx0 = fmaxf(mx0, __shfl_xor_sync(0xffffffffu, mx0, 2));
        mx1 = fmaxf(mx1, __shfl_xor_sync(0xffffffffu, mx1, 1));
        mx1 = fmaxf(mx1, __shfl_xor_sync(0xffffffffu, mx1, 2));
        if ((lane & 3) == 0) {
            pmax[wh * 64 + wm + r4] = mx0;
            pmax[wh * 64 + wm + 8 + r4] = mx1;
        }

        __syncthreads();

        float ma0 = fmaxf(pmax[wm + r4], pmax[64 + wm + r4]);
        float ma1 = fmaxf(pmax[wm + 8 + r4], pmax[64 + wm + 8 + r4]);
        float mn0 = fmaxf(mold0, ma0);
        float mn1 = fmaxf(mold1, ma1);
        float fs0 = __expf(mold0 - mn0);
        float fs1 = __expf(mold1 - mn1);
        mold0 = mn0; mold1 = mn1;

        float s0r = 0.f, s1r = 0.f;
#pragma unroll
        for (int nt = 0; nt < 4; nt++) {
            sa[nt][0] = __expf(sa[nt][0] - mn0);
            sa[nt][1] = __expf(sa[nt][1] - mn0);
            sa[nt][2] = __expf(sa[nt][2] - mn1);
            sa[nt][3] = __expf(sa[nt][3] - mn1);
            s0r += sa[nt][0] + sa[nt][1];
            s1r += sa[nt][2] + sa[nt][3];
        }
        s0r += __shfl_xor_sync(0xffffffffu, s0r, 1);
        s0r += __shfl_xor_sync(0xffffffffu, s0r, 2);
        s1r += __shfl_xor_sync(0xffffffffu, s1r, 1);
        s1r += __shfl_xor_sync(0xffffffffu, s1r, 2);
        lsum0 = lsum0 * fs0 + s0r;
        lsum1 = lsum1 * fs1 + s1r;

#pragma unroll
        for (int nt = 0; nt < 10; nt++) {
            acc[nt][0] *= fs0; acc[nt][1] *= fs0;
            acc[nt][2] *= fs1; acc[nt][3] *= fs1;
        }

#pragma unroll
        for (int kb = 0; kb < 2; kb++) {
            uint32_t aH[4];
            aH[0] = pkh(sa[2 * kb][0], sa[2 * kb][1]);
            aH[1] = pkh(sa[2 * kb][2], sa[2 * kb][3]);
            aH[2] = pkh(sa[2 * kb + 1][0], sa[2 * kb + 1][1]);
            aH[3] = pkh(sa[2 * kb + 1][2], sa[2 * kb + 1][3]);
            const int vrow = wn + kb * 16 + (lane & 15);
#pragma unroll
            for (int np = 0; np < 5; np++) {
                uint32_t vh4[4];
                uint32_t voff = (uint32_t)(vrow * ATS + (np * 16 + ((lane >> 4) << 3)) * 2);
                ldsm4t(vh4, sVH + voff);
                mma16816h(acc[np * 2], aH, vh4);
                mma16816h(acc[np * 2 + 1], aH, vh4 + 2);
            }
        }
    }

    float* cb = (float*)(sm + AK0);
    if (wh == 1) {
#pragma unroll
        for (int nt = 0; nt < 10; nt++) {
            int cc = nt * 8 + q2;
            cb[(wm + r4) * 80 + cc]     = acc[nt][0];
            cb[(wm + r4) * 80 + cc + 1] = acc[nt][1];
            cb[(wm + r4 + 8) * 80 + cc]     = acc[nt][2];
            cb[(wm + r4 + 8) * 80 + cc + 1] = acc[nt][3];
        }
        if ((lane & 3) == 0) {
            plsum[wm + r4] = lsum0;
            plsum[wm + r4 + 8] = lsum1;
        }
    }
    __syncthreads();
    if (wh == 0) {
        float li0 = 1.f / (lsum0 + plsum[wm + r4]);
        float li1 = 1.f / (lsum1 + plsum[wm + r4 + 8]);
        int gr0 = q0 + wm + r4;
#pragma unroll
        for (int nt = 0; nt < 10; nt++) {
            int col = h * HD + nt * 8 + q2;
            float x0 = (acc[nt][0] + cb[(wm + r4) * 80 + nt * 8 + q2]) * li0;
            float y0 = (acc[nt][1] + cb[(wm + r4) * 80 + nt * 8 + q2 + 1]) * li0;
            float x1 = (acc[nt][2] + cb[(wm + r4 + 8) * 80 + nt * 8 + q2]) * li1;
            float y1 = (acc[nt][3] + cb[(wm + r4 + 8) * 80 + nt * 8 + q2 + 1]) * li1;
            size_t a0 = (size_t)gr0 * DIM + col;
            size_t a1 = a0 + (size_t)8 * DIM;
            *(uint32_t*)(ch + a0) = pkh(x0, y0);
            *(uint32_t*)(ch + a1) = pkh(x1, y1);
        }
    }
}

// ---------------------------------------------------------------------------
extern "C" void kernel_launch(void* const* d_in, const int* in_sizes, int n_in,
                              void* d_out, int out_size)
{
    const float* hs   = (const float*)d_in[0];
    const float* cosb = (const float*)d_in[1];
    const float* sinb = (const float*)d_in[2];
    const float* wq   = (const float*)d_in[3];
    const float* bq   = (const float*)d_in[4];
    const float* wk   = (const float*)d_in[5];
    const float* bk   = (const float*)d_in[6];
    const float* wv   = (const float*)d_in[7];
    const float* bv   = (const float*)d_in[8];
    const float* wo   = (const float*)d_in[9];
    const float* bo   = (const float*)d_in[10];
    float* out = (float*)d_out;

    __half *ah, *wh, *ch, *qh, *kh, *vh;
    cudaGetSymbolAddress((void**)&ah, g_ah);
    cudaGetSymbolAddress((void**)&wh, g_wh);
    cudaGetSymbolAddress((void**)&ch, g_ch);
    cudaGetSymbolAddress((void**)&qh, g_qh);
    cudaGetSymbolAddress((void**)&kh, g_kh);
    cudaGetSymbolAddress((void**)&vh, g_vh);

    cudaFuncSetAttribute(gemm_qkv_rope,
                         cudaFuncAttributeMaxDynamicSharedMemorySize, QKV_SMEM);
    cudaFuncSetAttribute(gemm_hmma,
                         cudaFuncAttributeMaxDynamicSharedMemorySize, GEMM_SMEM);
    cudaFuncSetAttribute(attn_mma,
                         cudaFuncAttributeMaxDynamicSharedMemorySize, ATTN_SMEM);

    // 1) all fp32->fp16 conversions
    split_all<<<(HS4 + 4 * W4) / 256, 256>>>(
        (const float4*)hs, (const float4*)wq, (const float4*)wk,
        (const float4*)wv, (const float4*)wo, (uint2*)ah, (uint2*)wh);

    // 2) fused QKV projection + rope + per-head fp16 store
    gemm_qkv_rope<<<dim3(NH, S / 128, 3), 256, QKV_SMEM>>>(
        ah, wh, cosb, sinb, bq, bk, bv, qh, kh, vh);

    // 3) attention
    attn_mma<<<dim3(8, NH, NSEG), 256, ATTN_SMEM>>>(ch);

    // 4) O projection
    gemm_hmma<<<dim3(DIM / GBN, S / GBM, 1), 256, GEMM_SMEM>>>(
        ch, wh, 3, bo, out);
}